// round 3
// baseline (speedup 1.0000x reference)
#include <cuda_runtime.h>
#include <cuda_bf16.h>
#include <cstdint>

// Problem constants
#define PV 50000
#define PE 512
#define PH 512
#define PHD 256
#define PL 2
#define PK 32
#define PB 64
#define PT 256
#define G4 1024      // 4*HD
#define BT (PB*PT)   // 16384

// ---------------- device scratch (no allocation allowed) ----------------
__device__ float g_xA[BT * PE];
__device__ float g_xB[BT * PE];
__device__ float g_xrev[BT * PE];
__device__ float g_gx0[BT * G4];
__device__ float g_gx1[BT * G4];
__device__ float g_ht[2 * 2 * PB * PHD];   // [phase][dir][b][j]
__device__ float g_feats[BT * PK];
__device__ int   g_lens[PB];
__device__ unsigned g_ctr;

// ---------------- helpers ----------------
__device__ __forceinline__ float sigf(float x) { return 1.f / (1.f + __expf(-x)); }

// ---------------- lens ----------------
__global__ void k_lens(const int* __restrict__ sent) {
    int b = threadIdx.x;
    if (b < PB) {
        int c = 0;
        for (int t = 0; t < PT; t++) c += (sent[b * PT + t] > 0);
        g_lens[b] = c;
    }
}

// ---------------- embedding gather + mask ----------------
__global__ void k_embed(const int* __restrict__ sent, const float* __restrict__ embed) {
    int row = blockIdx.x;             // b*T + t
    int tid = threadIdx.x;            // 0..127, one float4 each
    int tok = sent[row];
    float4 v = make_float4(0.f, 0.f, 0.f, 0.f);
    if (tok > 0) v = ((const float4*)(embed + (size_t)tok * PE))[tid];
    ((float4*)(g_xA + (size_t)row * PE))[tid] = (blockIdx.y == 0) ? v : v; // placeholder
    // note: only used for layer-0 input; write directly:
}

// generic reverse-within-length copy: xrev[b][t] = xin[b][ridx(b,t)]
__global__ void k_reverse(const float* __restrict__ xin) {
    int row = blockIdx.x;
    int b = row >> 8, t = row & 255;
    int len = g_lens[b];
    int pos = (t < len) ? (len - 1 - t) : t;
    int tid = threadIdx.x;
    ((float4*)(g_xrev + (size_t)row * PE))[tid] =
        ((const float4*)(xin + ((size_t)(b * PT + pos)) * PE))[tid];
}

// ---------------- input-projection GEMM ----------------
// C[m][n] = sum_k A[m][k] * W[n][k] + bi[n] + bh[n]
// A: [16384][512], W: [1024][512], C: [16384][1024]; grid.z selects direction.
#define GBM 128
#define GBN 128
#define GBK 8
__global__ __launch_bounds__(256) void k_gemm_gx(
    const float* __restrict__ Afwd, const float* __restrict__ Abwd,
    const float* __restrict__ w_ih, const float* __restrict__ b_ih,
    const float* __restrict__ b_hh, int layer)
{
    int z = blockIdx.z;
    const float* A = z ? Abwd : Afwd;
    const float* W = w_ih + ((size_t)(layer * 2 + z)) * G4 * PE;
    const float* bi = b_ih + (layer * 2 + z) * G4;
    const float* bh = b_hh + (layer * 2 + z) * G4;
    float* C = z ? g_gx1 : g_gx0;

    __shared__ __align__(16) float As[GBK][GBM];
    __shared__ __align__(16) float Bs[GBK][GBN];

    int m0 = blockIdx.y * GBM;
    int n0 = blockIdx.x * GBN;
    int tid = threadIdx.x;
    int lr = tid >> 1;
    int lc = (tid & 1) * 4;
    int tx = tid & 15, ty = tid >> 4;

    float acc[8][8];
#pragma unroll
    for (int i = 0; i < 8; i++)
#pragma unroll
        for (int j = 0; j < 8; j++) acc[i][j] = 0.f;

    for (int k0 = 0; k0 < PE; k0 += GBK) {
        float4 av = *(const float4*)(A + (size_t)(m0 + lr) * PE + k0 + lc);
        float4 bv = *(const float4*)(W + (size_t)(n0 + lr) * PE + k0 + lc);
        As[lc + 0][lr] = av.x; As[lc + 1][lr] = av.y; As[lc + 2][lr] = av.z; As[lc + 3][lr] = av.w;
        Bs[lc + 0][lr] = bv.x; Bs[lc + 1][lr] = bv.y; Bs[lc + 2][lr] = bv.z; Bs[lc + 3][lr] = bv.w;
        __syncthreads();
#pragma unroll
        for (int kk = 0; kk < GBK; kk++) {
            float ar[8], br[8];
#pragma unroll
            for (int i = 0; i < 8; i++) ar[i] = As[kk][ty * 8 + i];
#pragma unroll
            for (int j = 0; j < 8; j++) br[j] = Bs[kk][tx * 8 + j];
#pragma unroll
            for (int i = 0; i < 8; i++)
#pragma unroll
                for (int j = 0; j < 8; j++) acc[i][j] += ar[i] * br[j];
        }
        __syncthreads();
    }
#pragma unroll
    for (int i = 0; i < 8; i++) {
        int m = m0 + ty * 8 + i;
#pragma unroll
        for (int j = 0; j < 8; j++) {
            int n = n0 + tx * 8 + j;
            C[(size_t)m * G4 + n] = acc[i][j] + bi[n] + bh[n];
        }
    }
}

// ---------------- reset (deterministic replays) ----------------
__global__ void k_reset() { g_ctr = 0u; }

// ---------------- persistent recurrent scan ----------------
#define NB 128
__device__ __forceinline__ void gbar(unsigned tgt) {
    __syncthreads();
    if (threadIdx.x == 0) {
        __threadfence();
        atomicAdd(&g_ctr, 1u);
        while (*((volatile unsigned*)&g_ctr) < tgt) {}
    }
    __syncthreads();
}

__global__ __launch_bounds__(256) void k_scan(const float* __restrict__ w_hh, int layer,
                                              float* __restrict__ xout)
{
    int bid = blockIdx.x;
    int d = bid & 1;            // direction
    int s = bid >> 1;           // hidden slice 0..63
    int j0 = s * 4;
    int tid = threadIdx.x;
    int q = tid & 3;            // unit within slice
    int b = tid >> 2;           // batch element
    int j = j0 + q;             // hidden unit owned by this thread

    __shared__ __align__(16) float w_s[16][260];  // rows: g*4 + unit
    const float* whh = w_hh + ((size_t)(layer * 2 + d)) * G4 * PHD;
#pragma unroll
    for (int c = 0; c < 4; c++) {
        int v = tid + c * 256;          // float4 index, 1024 total
        int r = v >> 6;                 // row 0..15
        int i4 = v & 63;
        int g = r >> 2, qq = r & 3;
        float4 wv = *(const float4*)(whh + (size_t)(g * PHD + j0 + qq) * PHD + i4 * 4);
        *(float4*)&w_s[r][i4 * 4] = wv;
    }

    // zero phase-0 hidden state (each (d,b,j) owned by exactly one thread)
    __stcg(&g_ht[((0 * 2 + d) * PB + b) * PHD + j], 0.f);

    unsigned tgt = NB;
    gbar(tgt);

    float cst = 0.f;
    int len = g_lens[b];
    const float* gx = (d ? g_gx1 : g_gx0) + (size_t)b * PT * G4;
    float* xo = xout + ((size_t)b * PT) * PH + d * PHD + j;

    const float4* w0 = (const float4*)&w_s[0 + q][0];
    const float4* w1 = (const float4*)&w_s[4 + q][0];
    const float4* w2 = (const float4*)&w_s[8 + q][0];
    const float4* w3 = (const float4*)&w_s[12 + q][0];

    for (int t = 0; t < PT; t++) {
        const float4* hp = (const float4*)(g_ht + (((t & 1) * 2 + d) * PB + b) * PHD);
        const float* gxt = gx + (size_t)t * G4;
        float a0 = gxt[j];
        float a1 = gxt[PHD + j];
        float a2 = gxt[2 * PHD + j];
        float a3 = gxt[3 * PHD + j];
#pragma unroll 16
        for (int i4 = 0; i4 < 64; i4++) {
            float4 hv = __ldcg(hp + i4);
            float4 x0 = w0[i4], x1 = w1[i4], x2 = w2[i4], x3 = w3[i4];
            a0 += hv.x * x0.x + hv.y * x0.y + hv.z * x0.z + hv.w * x0.w;
            a1 += hv.x * x1.x + hv.y * x1.y + hv.z * x1.z + hv.w * x1.w;
            a2 += hv.x * x2.x + hv.y * x2.y + hv.z * x2.z + hv.w * x2.w;
            a3 += hv.x * x3.x + hv.y * x3.y + hv.z * x3.z + hv.w * x3.w;
        }
        float ig = sigf(a0), fg = sigf(a1), gg = tanhf(a2), og = sigf(a3);
        cst = fg * cst + ig * gg;
        float h = og * tanhf(cst);
        __stcg(&g_ht[((((t + 1) & 1) * 2 + d) * PB + b) * PHD + j], h);

        int pos = (d == 0) ? t : ((t < len) ? (len - 1 - t) : t);
        xo[(size_t)pos * PH] = (t < len) ? h : 0.f;

        tgt += NB;
        gbar(tgt);
    }
}

// ---------------- FC: feats = x @ fc_w.T + fc_b ----------------
__global__ void k_feats(const float* __restrict__ x2, const float* __restrict__ fc_w,
                        const float* __restrict__ fc_b)
{
    int w = threadIdx.x >> 5, lane = threadIdx.x & 31;
    int row = blockIdx.x * 8 + w;
    const float4* xr = (const float4*)(x2 + (size_t)row * PH);
    const float4* wr = (const float4*)(fc_w + (size_t)lane * PH);
    float acc = fc_b[lane];
#pragma unroll 8
    for (int i = 0; i < PH / 4; i++) {
        float4 xv = xr[i];
        float4 wv = __ldg(wr + i);
        acc += xv.x * wv.x + xv.y * wv.y + xv.z * wv.z + xv.w * wv.w;
    }
    g_feats[(size_t)row * PK + lane] = acc;
}

// ---------------- Viterbi decode (one warp per batch elem) ----------------
__global__ void k_viterbi(const float* __restrict__ st, const float* __restrict__ tr,
                          const float* __restrict__ et,
                          float* __restrict__ scores_out, float* __restrict__ tags_out)
{
    int b = blockIdx.x;
    int lane = threadIdx.x;  // 0..31 == tag index
    __shared__ float trs[PK][PK + 1];
    __shared__ float delta[PK];
    __shared__ float fin_s[PK];
    __shared__ unsigned char ptr_s[PT][PK];

#pragma unroll
    for (int kp = 0; kp < PK; kp++) trs[kp][lane] = tr[kp * PK + lane];

    const float* fb = g_feats + (size_t)b * PT * PK;
    delta[lane] = st[lane] + fb[lane];
    int len = g_lens[b];
    __syncwarp();

    for (int t = 1; t < PT; t++) {
        float nd; int p;
        if (t < len) {
            float best = -3.4e38f; int arg = 0;
#pragma unroll
            for (int kp = 0; kp < PK; kp++) {
                float v = delta[kp] + trs[kp][lane];
                if (v > best) { best = v; arg = kp; }
            }
            nd = best + fb[t * PK + lane];
            p = arg;
        } else {
            nd = delta[lane];
            p = lane;
        }
        ptr_s[t][lane] = (unsigned char)p;
        __syncwarp();
        delta[lane] = nd;
        __syncwarp();
    }

    fin_s[lane] = delta[lane] + et[lane];
    __syncwarp();

    if (lane == 0) {
        float best = -3.4e38f; int last = 0;
        for (int k = 0; k < PK; k++)
            if (fin_s[k] > best) { best = fin_s[k]; last = k; }
        if (scores_out) scores_out[b] = best;
        if (tags_out) {
            float* tg = tags_out + (size_t)b * PT;
            tg[PT - 1] = (PT - 1 < len) ? (float)last : 0.f;
            int cur = last;
            for (int t = PT - 1; t >= 1; t--) {
                int prev = (int)ptr_s[t][cur];
                cur = prev;
                tg[t - 1] = (t - 1 < len) ? (float)prev : 0.f;
            }
        }
    }
}

// ---------------- launch ----------------
extern "C" void kernel_launch(void* const* d_in, const int* in_sizes, int n_in,
                              void* d_out, int out_size)
{
    const int*   sent  = (const int*)d_in[0];
    const float* embed = (const float*)d_in[1];
    const float* w_ih  = (const float*)d_in[2];
    const float* w_hh  = (const float*)d_in[3];
    const float* b_ih  = (const float*)d_in[4];
    const float* b_hh  = (const float*)d_in[5];
    const float* fc_w  = (const float*)d_in[6];
    const float* fc_b  = (const float*)d_in[7];
    const float* st    = (const float*)d_in[8];
    const float* tr    = (const float*)d_in[9];
    const float* et    = (const float*)d_in[10];

    float* out = (float*)d_out;
    float* scores_ptr = nullptr;
    float* tags_ptr = nullptr;
    if (out_size >= PB + BT)      { scores_ptr = out; tags_ptr = out + PB; }
    else if (out_size == BT)      { tags_ptr = out; }
    else                          { scores_ptr = out; }

    // resolve device-global addresses (host-side, cached-safe: deterministic)
    float *xA, *xB, *xrev;
    cudaGetSymbolAddress((void**)&xA,   g_xA);
    cudaGetSymbolAddress((void**)&xB,   g_xB);
    cudaGetSymbolAddress((void**)&xrev, g_xrev);

    k_lens<<<1, 64>>>(sent);
    k_embed<<<dim3(BT), 128>>>(sent, embed);

    for (int l = 0; l < PL; l++) {
        float* xin  = (l == 0) ? xA : xB;
        float* xout = (l == 0) ? xB : xA;
        k_reverse<<<dim3(BT), 128>>>(xin);
        k_gemm_gx<<<dim3(G4 / GBN, BT / GBM, 2), 256>>>(xin, xrev, w_ih, b_ih, b_hh, l);
        k_reset<<<1, 1>>>();
        k_scan<<<NB, 256>>>(w_hh, l, xout);
    }

    k_feats<<<BT / 8, 256>>>(xA, fc_w, fc_b);
    k_viterbi<<<PB, 32>>>(st, tr, et, scores_ptr, tags_ptr);
}

// round 4
// speedup vs baseline: 1.5123x; 1.5123x over previous
#include <cuda_runtime.h>
#include <cuda_bf16.h>
#include <cstdint>

// Problem constants
#define PV 50000
#define PE 512
#define PH 512
#define PHD 256
#define PL 2
#define PK 32
#define PB 64
#define PT 256
#define G4 1024      // 4*HD
#define BT (PB*PT)   // 16384

// ---------------- device scratch (no allocation allowed) ----------------
__device__ float g_xA[BT * PE];
__device__ float g_xB[BT * PE];
__device__ float g_xrev[BT * PE];
__device__ float g_gx0[BT * G4];
__device__ float g_gx1[BT * G4];
__device__ float g_ht[2 * 2 * PB * PHD];   // [phase][dir][b][j]
__device__ float g_feats[BT * PK];
__device__ int   g_lens[PB];
__device__ unsigned g_ctr;

// ---------------- helpers ----------------
__device__ __forceinline__ float sigf(float x) { return 1.f / (1.f + __expf(-x)); }

// ---------------- lens ----------------
__global__ void k_lens(const int* __restrict__ sent) {
    int b = threadIdx.x;
    if (b < PB) {
        int c = 0;
        for (int t = 0; t < PT; t++) c += (sent[b * PT + t] > 0);
        g_lens[b] = c;
    }
}

// ---------------- embedding gather + mask ----------------
__global__ void k_embed(const int* __restrict__ sent, const float* __restrict__ embed) {
    int row = blockIdx.x;             // b*T + t
    int tid = threadIdx.x;            // 0..127, one float4 each
    int tok = sent[row];
    float4 v = make_float4(0.f, 0.f, 0.f, 0.f);
    if (tok > 0) v = ((const float4*)(embed + (size_t)tok * PE))[tid];
    ((float4*)(g_xA + (size_t)row * PE))[tid] = v;
}

// reverse-within-length copy: xrev[b][t] = xin[b][ridx(b,t)]
__global__ void k_reverse(const float* __restrict__ xin) {
    int row = blockIdx.x;
    int b = row >> 8, t = row & 255;
    int len = g_lens[b];
    int pos = (t < len) ? (len - 1 - t) : t;
    int tid = threadIdx.x;
    ((float4*)(g_xrev + (size_t)row * PE))[tid] =
        ((const float4*)(xin + ((size_t)(b * PT + pos)) * PE))[tid];
}

// ---------------- input-projection GEMM ----------------
// C[m][n] = sum_k A[m][k] * W[n][k] + bi[n] + bh[n]
#define GBM 128
#define GBN 128
#define GBK 8
__global__ __launch_bounds__(256, 2) void k_gemm_gx(
    const float* __restrict__ Afwd, const float* __restrict__ Abwd,
    const float* __restrict__ w_ih, const float* __restrict__ b_ih,
    const float* __restrict__ b_hh, int layer)
{
    int z = blockIdx.z;
    const float* A = z ? Abwd : Afwd;
    const float* W = w_ih + ((size_t)(layer * 2 + z)) * G4 * PE;
    const float* bi = b_ih + (layer * 2 + z) * G4;
    const float* bh = b_hh + (layer * 2 + z) * G4;
    float* C = z ? g_gx1 : g_gx0;

    __shared__ __align__(16) float As[GBK][GBM];
    __shared__ __align__(16) float Bs[GBK][GBN];

    int m0 = blockIdx.y * GBM;
    int n0 = blockIdx.x * GBN;
    int tid = threadIdx.x;
    int lr = tid >> 1;
    int lc = (tid & 1) * 4;
    int tx = tid & 15, ty = tid >> 4;

    // bias hoist: this thread's 8 output columns
    float bsum[8];
#pragma unroll
    for (int j = 0; j < 8; j++) {
        int n = n0 + tx * 8 + j;
        bsum[j] = bi[n] + bh[n];
    }

    float acc[8][8];
#pragma unroll
    for (int i = 0; i < 8; i++)
#pragma unroll
        for (int j = 0; j < 8; j++) acc[i][j] = 0.f;

    for (int k0 = 0; k0 < PE; k0 += GBK) {
        float4 av = *(const float4*)(A + (size_t)(m0 + lr) * PE + k0 + lc);
        float4 bv = *(const float4*)(W + (size_t)(n0 + lr) * PE + k0 + lc);
        As[lc + 0][lr] = av.x; As[lc + 1][lr] = av.y; As[lc + 2][lr] = av.z; As[lc + 3][lr] = av.w;
        Bs[lc + 0][lr] = bv.x; Bs[lc + 1][lr] = bv.y; Bs[lc + 2][lr] = bv.z; Bs[lc + 3][lr] = bv.w;
        __syncthreads();
#pragma unroll
        for (int kk = 0; kk < GBK; kk++) {
            float ar[8], br[8];
#pragma unroll
            for (int i = 0; i < 8; i++) ar[i] = As[kk][ty * 8 + i];
#pragma unroll
            for (int j = 0; j < 8; j++) br[j] = Bs[kk][tx * 8 + j];
#pragma unroll
            for (int i = 0; i < 8; i++)
#pragma unroll
                for (int j = 0; j < 8; j++) acc[i][j] += ar[i] * br[j];
        }
        __syncthreads();
    }
#pragma unroll
    for (int i = 0; i < 8; i++) {
        int m = m0 + ty * 8 + i;
        float* cr = C + (size_t)m * G4 + n0 + tx * 8;
        float4 v0 = make_float4(acc[i][0] + bsum[0], acc[i][1] + bsum[1],
                                acc[i][2] + bsum[2], acc[i][3] + bsum[3]);
        float4 v1 = make_float4(acc[i][4] + bsum[4], acc[i][5] + bsum[5],
                                acc[i][6] + bsum[6], acc[i][7] + bsum[7]);
        *(float4*)(cr + 0) = v0;
        *(float4*)(cr + 4) = v1;
    }
}

// ---------------- reset (deterministic replays) ----------------
__global__ void k_reset() { g_ctr = 0u; }

// ---------------- persistent recurrent scan ----------------
#define NB 128
#define ROWW 260                 // padded row stride (floats) for bank spread
#define SH_H_OFF (16 * ROWW)     // w: rows 0..15, then h: 64 rows
#define SH_FLOATS ((16 + 64) * ROWW)

__device__ __forceinline__ void gbar(unsigned tgt) {
    __syncthreads();
    if (threadIdx.x == 0) {
        __threadfence();
        atomicAdd(&g_ctr, 1u);
        while (*((volatile unsigned*)&g_ctr) < tgt) {}
    }
    __syncthreads();
}

__global__ __launch_bounds__(256, 1) void k_scan(const float* __restrict__ w_hh, int layer,
                                                 float* __restrict__ xout)
{
    extern __shared__ float sh[];
    float* w_s = sh;                   // [16][ROWW] rows: g*4 + q
    float* h_s = sh + SH_H_OFF;        // [64][ROWW]

    int bid = blockIdx.x;
    int d = bid & 1;            // direction
    int s = bid >> 1;           // hidden slice 0..63
    int j0 = s * 4;
    int tid = threadIdx.x;
    int q = tid & 3;            // unit within slice
    int b = tid >> 2;           // batch element
    int j = j0 + q;             // hidden unit owned by this thread

    const float* whh = w_hh + ((size_t)(layer * 2 + d)) * G4 * PHD;
#pragma unroll
    for (int c = 0; c < 4; c++) {
        int v = tid + c * 256;          // float4 index, 1024 total
        int r = v >> 6;                 // row 0..15
        int i4 = v & 63;
        int g = r >> 2, qq = r & 3;
        float4 wv = *(const float4*)(whh + (size_t)(g * PHD + j0 + qq) * PHD + i4 * 4);
        *(float4*)&w_s[r * ROWW + i4 * 4] = wv;
    }

    // zero phase-0 hidden state (each (d,b,j) owned by exactly one thread)
    __stcg(&g_ht[((0 * 2 + d) * PB + b) * PHD + j], 0.f);

    unsigned tgt = NB;
    gbar(tgt);

    float cst = 0.f;
    int len = g_lens[b];
    const float* gx = (d ? g_gx1 : g_gx0) + (size_t)b * PT * G4;
    float* xo = xout + ((size_t)b * PT) * PH + d * PHD + j;

    const float4* w0 = (const float4*)&w_s[(0 + q) * ROWW];
    const float4* w1 = (const float4*)&w_s[(4 + q) * ROWW];
    const float4* w2 = (const float4*)&w_s[(8 + q) * ROWW];
    const float4* w3 = (const float4*)&w_s[(12 + q) * ROWW];
    const float4* hrow = (const float4*)&h_s[b * ROWW];

    for (int t = 0; t < PT; t++) {
        // stage full h (this direction, all 64 batches) into shared, coalesced
        {
            const float4* hsrc = (const float4*)(g_ht + (size_t)((t & 1) * 2 + d) * PB * PHD);
#pragma unroll
            for (int c = 0; c < 16; c++) {
                int v = tid + c * 256;          // 4096 float4 total = 64KB
                int bb = v >> 6, i4 = v & 63;
                float4 hv = __ldcg(hsrc + v);
                *(float4*)&h_s[bb * ROWW + i4 * 4] = hv;
            }
        }
        __syncthreads();

        const float* gxt = gx + (size_t)t * G4;
        float a0 = gxt[j];
        float a1 = gxt[PHD + j];
        float a2 = gxt[2 * PHD + j];
        float a3 = gxt[3 * PHD + j];

#pragma unroll 4
        for (int i4 = 0; i4 < 64; i4++) {
            float4 hv = hrow[i4];
            float4 x0 = w0[i4], x1 = w1[i4], x2 = w2[i4], x3 = w3[i4];
            a0 += hv.x * x0.x + hv.y * x0.y + hv.z * x0.z + hv.w * x0.w;
            a1 += hv.x * x1.x + hv.y * x1.y + hv.z * x1.z + hv.w * x1.w;
            a2 += hv.x * x2.x + hv.y * x2.y + hv.z * x2.z + hv.w * x2.w;
            a3 += hv.x * x3.x + hv.y * x3.y + hv.z * x3.z + hv.w * x3.w;
        }
        float ig = sigf(a0), fg = sigf(a1), gg = tanhf(a2), og = sigf(a3);
        cst = fg * cst + ig * gg;
        float h = og * tanhf(cst);
        __stcg(&g_ht[((((t + 1) & 1) * 2 + d) * PB + b) * PHD + j], h);

        int pos = (d == 0) ? t : ((t < len) ? (len - 1 - t) : t);
        xo[(size_t)pos * PH] = (t < len) ? h : 0.f;

        if (t < PT - 1) {
            tgt += NB;
            gbar(tgt);
        }
    }
}

// ---------------- FC: feats = x @ fc_w.T + fc_b ----------------
__global__ void k_feats(const float* __restrict__ x2, const float* __restrict__ fc_w,
                        const float* __restrict__ fc_b)
{
    int w = threadIdx.x >> 5, lane = threadIdx.x & 31;
    int row = blockIdx.x * 8 + w;
    const float4* xr = (const float4*)(x2 + (size_t)row * PH);
    const float4* wr = (const float4*)(fc_w + (size_t)lane * PH);
    float acc = fc_b[lane];
#pragma unroll 8
    for (int i = 0; i < PH / 4; i++) {
        float4 xv = xr[i];
        float4 wv = __ldg(wr + i);
        acc += xv.x * wv.x + xv.y * wv.y + xv.z * wv.z + xv.w * wv.w;
    }
    g_feats[(size_t)row * PK + lane] = acc;
}

// ---------------- Viterbi decode (one warp per batch elem) ----------------
__global__ void k_viterbi(const float* __restrict__ st, const float* __restrict__ tr,
                          const float* __restrict__ et,
                          float* __restrict__ scores_out, float* __restrict__ tags_out)
{
    int b = blockIdx.x;
    int lane = threadIdx.x;  // 0..31 == tag index
    __shared__ float trs[PK][PK + 1];
    __shared__ float delta[PK];
    __shared__ float fin_s[PK];
    __shared__ unsigned char ptr_s[PT][PK];

#pragma unroll
    for (int kp = 0; kp < PK; kp++) trs[kp][lane] = tr[kp * PK + lane];

    const float* fb = g_feats + (size_t)b * PT * PK;
    delta[lane] = st[lane] + fb[lane];
    int len = g_lens[b];
    __syncwarp();

    for (int t = 1; t < PT; t++) {
        float nd; int p;
        if (t < len) {
            float best = -3.4e38f; int arg = 0;
#pragma unroll
            for (int kp = 0; kp < PK; kp++) {
                float v = delta[kp] + trs[kp][lane];
                if (v > best) { best = v; arg = kp; }
            }
            nd = best + fb[t * PK + lane];
            p = arg;
        } else {
            nd = delta[lane];
            p = lane;
        }
        ptr_s[t][lane] = (unsigned char)p;
        __syncwarp();
        delta[lane] = nd;
        __syncwarp();
    }

    fin_s[lane] = delta[lane] + et[lane];
    __syncwarp();

    if (lane == 0) {
        float best = -3.4e38f; int last = 0;
        for (int k = 0; k < PK; k++)
            if (fin_s[k] > best) { best = fin_s[k]; last = k; }
        if (scores_out) scores_out[b] = best;
        if (tags_out) {
            float* tg = tags_out + (size_t)b * PT;
            tg[PT - 1] = (PT - 1 < len) ? (float)last : 0.f;
            int cur = last;
            for (int t = PT - 1; t >= 1; t--) {
                int prev = (int)ptr_s[t][cur];
                cur = prev;
                tg[t - 1] = (t - 1 < len) ? (float)prev : 0.f;
            }
        }
    }
}

// ---------------- launch ----------------
extern "C" void kernel_launch(void* const* d_in, const int* in_sizes, int n_in,
                              void* d_out, int out_size)
{
    const int*   sent  = (const int*)d_in[0];
    const float* embed = (const float*)d_in[1];
    const float* w_ih  = (const float*)d_in[2];
    const float* w_hh  = (const float*)d_in[3];
    const float* b_ih  = (const float*)d_in[4];
    const float* b_hh  = (const float*)d_in[5];
    const float* fc_w  = (const float*)d_in[6];
    const float* fc_b  = (const float*)d_in[7];
    const float* st    = (const float*)d_in[8];
    const float* tr    = (const float*)d_in[9];
    const float* et    = (const float*)d_in[10];

    float* out = (float*)d_out;
    float* scores_ptr = nullptr;
    float* tags_ptr = nullptr;
    if (out_size >= PB + BT)      { scores_ptr = out; tags_ptr = out + PB; }
    else if (out_size == BT)      { tags_ptr = out; }
    else                          { scores_ptr = out; }

    float *xA, *xB, *xrev;
    cudaGetSymbolAddress((void**)&xA,   g_xA);
    cudaGetSymbolAddress((void**)&xB,   g_xB);
    cudaGetSymbolAddress((void**)&xrev, g_xrev);

    static bool attr_done = false;
    if (!attr_done) {
        cudaFuncSetAttribute(k_scan, cudaFuncAttributeMaxDynamicSharedMemorySize,
                             SH_FLOATS * (int)sizeof(float));
        attr_done = true;
    }

    k_lens<<<1, 64>>>(sent);
    k_embed<<<dim3(BT), 128>>>(sent, embed);

    for (int l = 0; l < PL; l++) {
        float* xin  = (l == 0) ? xA : xB;
        float* xout = (l == 0) ? xB : xA;
        k_reverse<<<dim3(BT), 128>>>(xin);
        k_gemm_gx<<<dim3(G4 / GBN, BT / GBM, 2), 256>>>(xin, xrev, w_ih, b_ih, b_hh, l);
        k_reset<<<1, 1>>>();
        k_scan<<<NB, 256, SH_FLOATS * (int)sizeof(float)>>>(w_hh, l, xout);
    }

    k_feats<<<BT / 8, 256>>>(xA, fc_w, fc_b);
    k_viterbi<<<PB, 32>>>(st, tr, et, scores_ptr, tags_ptr);
}

// round 5
// speedup vs baseline: 1.9917x; 1.3170x over previous
#include <cuda_runtime.h>
#include <cuda_bf16.h>
#include <cstdint>

// Problem constants
#define PV 50000
#define PE 512
#define PH 512
#define PHD 256
#define PL 2
#define PK 32
#define PB 64
#define PT 256
#define G4 1024      // 4*HD
#define BT (PB*PT)   // 16384

// ---------------- device scratch (no allocation allowed) ----------------
__device__ float g_xA[BT * PE];
__device__ float g_xB[BT * PE];
__device__ float g_gx0[BT * G4];
__device__ float g_gx1[BT * G4];
__device__ float g_ht[2 * 2 * PB * PHD];   // [phase][dir][b][j]
__device__ float g_feats[BT * PK];
__device__ int   g_lens[PB];
__device__ unsigned g_ctr;

// ---------------- helpers ----------------
__device__ __forceinline__ float sigf(float x) { return 1.f / (1.f + __expf(-x)); }

// ---------------- lens ----------------
__global__ void k_lens(const int* __restrict__ sent) {
    int b = threadIdx.x;
    if (b < PB) {
        int c = 0;
        for (int t = 0; t < PT; t++) c += (sent[b * PT + t] > 0);
        g_lens[b] = c;
    }
}

// ---------------- embedding gather + mask ----------------
__global__ void k_embed(const int* __restrict__ sent, const float* __restrict__ embed) {
    int row = blockIdx.x;             // b*T + t
    int tid = threadIdx.x;            // 0..127, one float4 each
    int tok = sent[row];
    float4 v = make_float4(0.f, 0.f, 0.f, 0.f);
    if (tok > 0) v = ((const float4*)(embed + (size_t)tok * PE))[tid];
    ((float4*)(g_xA + (size_t)row * PE))[tid] = v;
}

// ---------------- input-projection GEMM ----------------
// C[m][n] = sum_k A[row(m)][k] * W[n][k] + bi[n] + bh[n]
// z=1 gathers A rows through the reverse-within-length map (no xrev buffer).
#define GBM 128
#define GBN 128
#define GBK 8
__global__ __launch_bounds__(256, 2) void k_gemm_gx(
    const float* __restrict__ Ain,
    const float* __restrict__ w_ih, const float* __restrict__ b_ih,
    const float* __restrict__ b_hh, int layer)
{
    int z = blockIdx.z;
    const float* W = w_ih + ((size_t)(layer * 2 + z)) * G4 * PE;
    const float* bi = b_ih + (layer * 2 + z) * G4;
    const float* bh = b_hh + (layer * 2 + z) * G4;
    float* C = z ? g_gx1 : g_gx0;

    __shared__ __align__(16) float As[2][GBK][GBM];
    __shared__ __align__(16) float Bs[2][GBK][GBN];

    int m0 = blockIdx.y * GBM;
    int n0 = blockIdx.x * GBN;
    int tid = threadIdx.x;
    int lr = tid >> 1;
    int lc = (tid & 1) * 4;
    int tx = tid & 15, ty = tid >> 4;

    // A-row mapping (reverse-within-length for the backward direction)
    int arow = m0 + lr;
    if (z) {
        int bb = arow >> 8, tt = arow & 255;
        int ln = g_lens[bb];
        int pos = (tt < ln) ? (ln - 1 - tt) : tt;
        arow = (bb << 8) + pos;
    }
    const float* Arow = Ain + (size_t)arow * PE;
    const float* Wrow = W + (size_t)(n0 + lr) * PE;

    // bias hoist
    float bsum[8];
#pragma unroll
    for (int j = 0; j < 8; j++) {
        int n = n0 + tx * 8 + j;
        bsum[j] = bi[n] + bh[n];
    }

    float acc[8][8];
#pragma unroll
    for (int i = 0; i < 8; i++)
#pragma unroll
        for (int j = 0; j < 8; j++) acc[i][j] = 0.f;

    // prologue: load + store tile 0
    float4 av = *(const float4*)(Arow + lc);
    float4 bv = *(const float4*)(Wrow + lc);
    As[0][lc + 0][lr] = av.x; As[0][lc + 1][lr] = av.y; As[0][lc + 2][lr] = av.z; As[0][lc + 3][lr] = av.w;
    Bs[0][lc + 0][lr] = bv.x; Bs[0][lc + 1][lr] = bv.y; Bs[0][lc + 2][lr] = bv.z; Bs[0][lc + 3][lr] = bv.w;
    __syncthreads();

    int buf = 0;
    for (int k0 = 0; k0 < PE; k0 += GBK) {
        bool nx = (k0 + GBK < PE);
        float4 av2, bv2;
        if (nx) {
            av2 = *(const float4*)(Arow + k0 + GBK + lc);
            bv2 = *(const float4*)(Wrow + k0 + GBK + lc);
        }
#pragma unroll
        for (int kk = 0; kk < GBK; kk++) {
            float ar[8], br[8];
#pragma unroll
            for (int i = 0; i < 8; i++) ar[i] = As[buf][kk][ty * 8 + i];
#pragma unroll
            for (int j = 0; j < 8; j++) br[j] = Bs[buf][kk][tx * 8 + j];
#pragma unroll
            for (int i = 0; i < 8; i++)
#pragma unroll
                for (int j = 0; j < 8; j++) acc[i][j] += ar[i] * br[j];
        }
        if (nx) {
            int nb = buf ^ 1;
            As[nb][lc + 0][lr] = av2.x; As[nb][lc + 1][lr] = av2.y; As[nb][lc + 2][lr] = av2.z; As[nb][lc + 3][lr] = av2.w;
            Bs[nb][lc + 0][lr] = bv2.x; Bs[nb][lc + 1][lr] = bv2.y; Bs[nb][lc + 2][lr] = bv2.z; Bs[nb][lc + 3][lr] = bv2.w;
        }
        __syncthreads();
        buf ^= 1;
    }

#pragma unroll
    for (int i = 0; i < 8; i++) {
        int m = m0 + ty * 8 + i;
        float* cr = C + (size_t)m * G4 + n0 + tx * 8;
        float4 v0 = make_float4(acc[i][0] + bsum[0], acc[i][1] + bsum[1],
                                acc[i][2] + bsum[2], acc[i][3] + bsum[3]);
        float4 v1 = make_float4(acc[i][4] + bsum[4], acc[i][5] + bsum[5],
                                acc[i][6] + bsum[6], acc[i][7] + bsum[7]);
        *(float4*)(cr + 0) = v0;
        *(float4*)(cr + 4) = v1;
    }
}

// ---------------- reset (deterministic replays) ----------------
__global__ void k_reset() { g_ctr = 0u; }

// ---------------- persistent recurrent scan ----------------
#define NB 128
#define ROWW 260                     // padded row stride (floats)
#define SH_H_OFF (16 * ROWW)         // w rows 0..15, then h rows 0..63
#define SH_FLOATS (SH_H_OFF + 64 * ROWW)

__device__ __forceinline__ void gbar(unsigned tgt) {
    __syncthreads();
    if (threadIdx.x == 0) {
        __threadfence();
        atomicAdd(&g_ctr, 1u);
        while (*((volatile unsigned*)&g_ctr) < tgt) {}
    }
    __syncthreads();
}

__global__ __launch_bounds__(256, 1) void k_scan(const float* __restrict__ w_hh, int layer,
                                                 float* __restrict__ xout)
{
    extern __shared__ float sh[];
    float* w_s = sh;                   // [16][ROWW]
    float* h_s = sh + SH_H_OFF;        // [64][ROWW]
    float* cmb = h_s;                  // reused after mainloop each step

    int bid = blockIdx.x;
    int d = bid & 1;            // direction
    int s = bid >> 1;           // hidden slice 0..63
    int j0 = s * 4;
    int tid = threadIdx.x;

    // mainloop identity: 8 i-octants x 8 batch-groups x 4 units
    int iq   = tid & 7;
    int bgrp = (tid >> 3) & 7;
    int qm   = tid >> 6;
    int b0   = bgrp * 8;

    // owner identity: 4 units x 64 batches
    int q2 = tid & 3;
    int b2 = tid >> 2;
    int jown = j0 + q2;

    // load W_hh slice into shared (rows r = g*4 + unit)
    const float* whh = w_hh + ((size_t)(layer * 2 + d)) * G4 * PHD;
#pragma unroll
    for (int c = 0; c < 4; c++) {
        int v = tid + c * 256;
        int r = v >> 6, i4 = v & 63;
        int g = r >> 2, qq = r & 3;
        float4 wv = *(const float4*)(whh + (size_t)(g * PHD + j0 + qq) * PHD + i4 * 4);
        *(float4*)&w_s[r * ROWW + i4 * 4] = wv;
    }

    // zero phase-0 hidden state
    __stcg(&g_ht[((0 * 2 + d) * PB + b2) * PHD + jown], 0.f);

    int len = g_lens[b2];
    const float* gxo = (d ? g_gx1 : g_gx0) + (size_t)b2 * PT * G4;
    float* xo = xout + ((size_t)b2 * PT) * PH + d * PHD + jown;

    // prefetch gx for t=0 (independent of barrier)
    float ga0 = gxo[jown], ga1 = gxo[PHD + jown],
          ga2 = gxo[2 * PHD + jown], ga3 = gxo[3 * PHD + jown];

    unsigned tgt = NB;
    gbar(tgt);

    float cst = 0.f;

    const float4* wq0 = (const float4*)&w_s[(0 * 4 + qm) * ROWW];
    const float4* wq1 = (const float4*)&w_s[(1 * 4 + qm) * ROWW];
    const float4* wq2 = (const float4*)&w_s[(2 * 4 + qm) * ROWW];
    const float4* wq3 = (const float4*)&w_s[(3 * 4 + qm) * ROWW];

    for (int t = 0; t < PT; t++) {
        // stage h (this phase+direction) into shared, coalesced
        const float4* hsrc = (const float4*)(g_ht + (size_t)((t & 1) * 2 + d) * PB * PHD);
#pragma unroll
        for (int c = 0; c < 16; c++) {
            int v = tid + c * 256;
            int bb = v >> 6, i4 = v & 63;
            float4 hv = __ldcg(hsrc + v);
            *(float4*)&h_s[bb * ROWW + i4 * 4] = hv;
        }
        __syncthreads();

        // register-tiled partial matvec: 4 gates x 8 batches, i-range interleaved
        float acc[4][8];
#pragma unroll
        for (int g = 0; g < 4; g++)
#pragma unroll
            for (int bi = 0; bi < 8; bi++) acc[g][bi] = 0.f;

#pragma unroll 2
        for (int k = 0; k < 8; k++) {
            int i4 = iq + 8 * k;
            float4 x0 = wq0[i4], x1 = wq1[i4], x2 = wq2[i4], x3 = wq3[i4];
#pragma unroll
            for (int bi = 0; bi < 8; bi++) {
                float4 hv = *(const float4*)&h_s[(b0 + bi) * ROWW + i4 * 4];
                acc[0][bi] += hv.x * x0.x + hv.y * x0.y + hv.z * x0.z + hv.w * x0.w;
                acc[1][bi] += hv.x * x1.x + hv.y * x1.y + hv.z * x1.z + hv.w * x1.w;
                acc[2][bi] += hv.x * x2.x + hv.y * x2.y + hv.z * x2.z + hv.w * x2.w;
                acc[3][bi] += hv.x * x3.x + hv.y * x3.y + hv.z * x3.z + hv.w * x3.w;
            }
        }
        __syncthreads();   // h_s reads done; reuse region as cmb

        // scatter partials (stride-69 rows: conflict-free)
#pragma unroll
        for (int g = 0; g < 4; g++)
#pragma unroll
            for (int bi = 0; bi < 8; bi++)
                cmb[(32 * g + 8 * qm + iq) * 69 + b0 + bi] = acc[g][bi];
        __syncthreads();

        // owner combine + nonlinearity
        float a0 = ga0, a1 = ga1, a2 = ga2, a3 = ga3;
#pragma unroll
        for (int i = 0; i < 8; i++) {
            a0 += cmb[(32 * 0 + 8 * q2 + i) * 69 + b2];
            a1 += cmb[(32 * 1 + 8 * q2 + i) * 69 + b2];
            a2 += cmb[(32 * 2 + 8 * q2 + i) * 69 + b2];
            a3 += cmb[(32 * 3 + 8 * q2 + i) * 69 + b2];
        }
        float ig = sigf(a0), fg = sigf(a1), gg = tanhf(a2), og = sigf(a3);
        cst = fg * cst + ig * gg;
        float h = og * tanhf(cst);
        __stcg(&g_ht[((((t + 1) & 1) * 2 + d) * PB + b2) * PHD + jown], h);

        int pos = (d == 0) ? t : ((t < len) ? (len - 1 - t) : t);
        xo[(size_t)pos * PH] = (t < len) ? h : 0.f;

        if (t < PT - 1) {
            // prefetch next step's gx before the barrier
            const float* gxt = gxo + (size_t)(t + 1) * G4;
            ga0 = gxt[jown]; ga1 = gxt[PHD + jown];
            ga2 = gxt[2 * PHD + jown]; ga3 = gxt[3 * PHD + jown];
            tgt += NB;
            gbar(tgt);
        }
    }
}

// ---------------- FC: feats = x @ fc_w.T + fc_b ----------------
__global__ void k_feats(const float* __restrict__ x2, const float* __restrict__ fc_w,
                        const float* __restrict__ fc_b)
{
    int w = threadIdx.x >> 5, lane = threadIdx.x & 31;
    int row = blockIdx.x * 8 + w;
    const float4* xr = (const float4*)(x2 + (size_t)row * PH);
    const float4* wr = (const float4*)(fc_w + (size_t)lane * PH);
    float acc = fc_b[lane];
#pragma unroll 8
    for (int i = 0; i < PH / 4; i++) {
        float4 xv = xr[i];
        float4 wv = __ldg(wr + i);
        acc += xv.x * wv.x + xv.y * wv.y + xv.z * wv.z + xv.w * wv.w;
    }
    g_feats[(size_t)row * PK + lane] = acc;
}

// ---------------- Viterbi decode (one warp per batch elem) ----------------
__global__ void k_viterbi(const float* __restrict__ st, const float* __restrict__ tr,
                          const float* __restrict__ et,
                          float* __restrict__ scores_out, float* __restrict__ tags_out)
{
    int b = blockIdx.x;
    int lane = threadIdx.x;  // 0..31 == tag index
    __shared__ float trs[PK][PK + 1];
    __shared__ float delta[PK];
    __shared__ float fin_s[PK];
    __shared__ unsigned char ptr_s[PT][PK];

#pragma unroll
    for (int kp = 0; kp < PK; kp++) trs[kp][lane] = tr[kp * PK + lane];

    const float* fb = g_feats + (size_t)b * PT * PK;
    delta[lane] = st[lane] + fb[lane];
    int len = g_lens[b];
    __syncwarp();

    for (int t = 1; t < PT; t++) {
        float nd; int p;
        if (t < len) {
            float best = -3.4e38f; int arg = 0;
#pragma unroll
            for (int kp = 0; kp < PK; kp++) {
                float v = delta[kp] + trs[kp][lane];
                if (v > best) { best = v; arg = kp; }
            }
            nd = best + fb[t * PK + lane];
            p = arg;
        } else {
            nd = delta[lane];
            p = lane;
        }
        ptr_s[t][lane] = (unsigned char)p;
        __syncwarp();
        delta[lane] = nd;
        __syncwarp();
    }

    fin_s[lane] = delta[lane] + et[lane];
    __syncwarp();

    if (lane == 0) {
        float best = -3.4e38f; int last = 0;
        for (int k = 0; k < PK; k++)
            if (fin_s[k] > best) { best = fin_s[k]; last = k; }
        if (scores_out) scores_out[b] = best;
        if (tags_out) {
            float* tg = tags_out + (size_t)b * PT;
            tg[PT - 1] = (PT - 1 < len) ? (float)last : 0.f;
            int cur = last;
            for (int t = PT - 1; t >= 1; t--) {
                int prev = (int)ptr_s[t][cur];
                cur = prev;
                tg[t - 1] = (t - 1 < len) ? (float)prev : 0.f;
            }
        }
    }
}

// ---------------- launch ----------------
extern "C" void kernel_launch(void* const* d_in, const int* in_sizes, int n_in,
                              void* d_out, int out_size)
{
    const int*   sent  = (const int*)d_in[0];
    const float* embed = (const float*)d_in[1];
    const float* w_ih  = (const float*)d_in[2];
    const float* w_hh  = (const float*)d_in[3];
    const float* b_ih  = (const float*)d_in[4];
    const float* b_hh  = (const float*)d_in[5];
    const float* fc_w  = (const float*)d_in[6];
    const float* fc_b  = (const float*)d_in[7];
    const float* st    = (const float*)d_in[8];
    const float* tr    = (const float*)d_in[9];
    const float* et    = (const float*)d_in[10];

    float* out = (float*)d_out;
    float* scores_ptr = nullptr;
    float* tags_ptr = nullptr;
    if (out_size >= PB + BT)      { scores_ptr = out; tags_ptr = out + PB; }
    else if (out_size == BT)      { tags_ptr = out; }
    else                          { scores_ptr = out; }

    float *xA, *xB;
    cudaGetSymbolAddress((void**)&xA, g_xA);
    cudaGetSymbolAddress((void**)&xB, g_xB);

    cudaFuncSetAttribute(k_scan, cudaFuncAttributeMaxDynamicSharedMemorySize,
                         SH_FLOATS * (int)sizeof(float));

    k_lens<<<1, 64>>>(sent);
    k_embed<<<dim3(BT), 128>>>(sent, embed);

    for (int l = 0; l < PL; l++) {
        float* xin  = (l == 0) ? xA : xB;
        float* xout = (l == 0) ? xB : xA;
        k_gemm_gx<<<dim3(G4 / GBN, BT / GBM, 2), 256>>>(xin, w_ih, b_ih, b_hh, l);
        k_reset<<<1, 1>>>();
        k_scan<<<NB, 256, SH_FLOATS * (int)sizeof(float)>>>(w_hh, l, xout);
    }

    k_feats<<<BT / 8, 256>>>(xA, fc_w, fc_b);
    k_viterbi<<<PB, 32>>>(st, tr, et, scores_ptr, tags_ptr);
}